// round 1
// baseline (speedup 1.0000x reference)
#include <cuda_runtime.h>
#include <math.h>

#define HID 128
#define NN 20000
#define NE 640000
#define ND 100000

// scratch (device globals: allocation-free contract)
__device__ float g_hn0[(size_t)NN * HID];
__device__ float g_hn1[(size_t)NN * HID];
__device__ float g_he [(size_t)NE * HID];
__device__ float g_agg[(size_t)NN * HID];

// ---------------------------------------------------------------- node embed
__global__ void node_embed(const float* __restrict__ x, const float* __restrict__ W,
                           const float* __restrict__ b)
{
    __shared__ float Ws[32 * HID];
    __shared__ float xs[16][33];
    int tid = threadIdx.x; // 128
    for (int i = tid; i < 32 * HID; i += 128) Ws[i] = W[i];
    int row0 = blockIdx.x * 16;
    for (int i = tid; i < 16 * 32; i += 128) xs[i >> 5][i & 31] = x[(size_t)row0 * 32 + i];
    float bb = b[tid];
    __syncthreads();
#pragma unroll 4
    for (int r = 0; r < 16; r++) {
        float acc = bb;
#pragma unroll
        for (int k = 0; k < 32; k++) acc = fmaf(xs[r][k], Ws[k * HID + tid], acc);
        g_hn0[(size_t)(row0 + r) * HID + tid] = fmaxf(acc, 0.f);
    }
}

// ---------------------------------------------------------------- edge embed
__global__ void edge_embed(const float* __restrict__ x, const float* __restrict__ W,
                           const float* __restrict__ b)
{
    __shared__ float Ws[16 * HID];
    __shared__ float xs[64][17];
    int tid = threadIdx.x; // 128
    for (int i = tid; i < 16 * HID; i += 128) Ws[i] = W[i];
    size_t row0 = (size_t)blockIdx.x * 64;
    for (int i = tid; i < 64 * 16; i += 128) xs[i >> 4][i & 15] = x[row0 * 16 + i];
    float bb = b[tid];
    __syncthreads();
#pragma unroll 4
    for (int r = 0; r < 64; r++) {
        float acc = bb;
#pragma unroll
        for (int k = 0; k < 16; k++) acc = fmaf(xs[r][k], Ws[k * HID + tid], acc);
        g_he[(row0 + r) * HID + tid] = fmaxf(acc, 0.f);
    }
}

// ---------------------------------------------------------------- zero agg
__global__ void zero_agg()
{
    size_t i = (size_t)blockIdx.x * blockDim.x + threadIdx.x;
    if (i < (size_t)NN * HID / 4) ((float4*)g_agg)[i] = make_float4(0.f, 0.f, 0.f, 0.f);
}

// ------------------------------------------------- fused message GEMM + segsum
// A[e] = [hn[src[e]] | he[e] | hn[dst[e]]] (K=384), B = W (384x128)
// out: atomicAdd relu(A@B + b) into g_agg[dst[e]]
__global__ void __launch_bounds__(256, 2)
msg_gemm(int layer, const int* __restrict__ eidx,
         const float* __restrict__ W, const float* __restrict__ bias)
{
    const float* __restrict__ hn = layer ? g_hn1 : g_hn0;
    __shared__ __align__(16) float As[16][132];
    __shared__ __align__(16) float Bs[16][132];
    __shared__ int   sSrc[128];
    __shared__ int   sDst[128];
    __shared__ float sB[128];

    const int tid   = threadIdx.x;
    const int eBase = blockIdx.x * 128;
    if (tid < 128) { sSrc[tid] = eidx[eBase + tid]; sB[tid] = bias[tid]; }
    else           { sDst[tid - 128] = eidx[NE + eBase + tid - 128]; }
    __syncthreads();

    const int arow = tid >> 1;
    const int akl  = (tid & 1) * 8;
    const int tx   = tid & 15, ty = tid >> 4;

    float acc[2][4][2][4];
#pragma unroll
    for (int a = 0; a < 2; a++)
#pragma unroll
        for (int i = 0; i < 4; i++)
#pragma unroll
            for (int b2 = 0; b2 < 2; b2++)
#pragma unroll
                for (int j = 0; j < 4; j++) acc[a][i][b2][j] = 0.f;

    float4 apf0, apf1, bpf0, bpf1;
    { // prefetch chunk 0 (seg 0 = hn[src])
        const float* base = hn + (size_t)sSrc[arow] * HID;
        apf0 = *(const float4*)(base + akl);
        apf1 = *(const float4*)(base + akl + 4);
        const float4* wb = (const float4*)W;
        bpf0 = wb[tid]; bpf1 = wb[tid + 256];
    }

    for (int t = 0; t < 24; t++) {
        // regs -> smem
        As[akl + 0][arow] = apf0.x; As[akl + 1][arow] = apf0.y;
        As[akl + 2][arow] = apf0.z; As[akl + 3][arow] = apf0.w;
        As[akl + 4][arow] = apf1.x; As[akl + 5][arow] = apf1.y;
        As[akl + 6][arow] = apf1.z; As[akl + 7][arow] = apf1.w;
        {
            int k0 = tid >> 5, c0 = (tid & 31) * 4;
            *(float4*)&Bs[k0][c0]     = bpf0;
            *(float4*)&Bs[k0 + 8][c0] = bpf1;
        }
        __syncthreads();
        if (t < 23) { // prefetch next chunk
            int kb = (t + 1) * 16;
            int seg = kb >> 7, off = kb & 127;
            const float* base = (seg == 0) ? hn + (size_t)sSrc[arow] * HID + off
                              : (seg == 1) ? g_he + (size_t)(eBase + arow) * HID + off
                                           : hn + (size_t)sDst[arow] * HID + off;
            apf0 = *(const float4*)(base + akl);
            apf1 = *(const float4*)(base + akl + 4);
            const float4* wb = (const float4*)(W + (size_t)kb * HID);
            bpf0 = wb[tid]; bpf1 = wb[tid + 256];
        }
#pragma unroll
        for (int k = 0; k < 16; k++) {
            float4 a0 = *(const float4*)&As[k][ty * 4];
            float4 a1 = *(const float4*)&As[k][64 + ty * 4];
            float4 b0 = *(const float4*)&Bs[k][tx * 4];
            float4 b1 = *(const float4*)&Bs[k][64 + tx * 4];
            float ar[8] = {a0.x, a0.y, a0.z, a0.w, a1.x, a1.y, a1.z, a1.w};
            float br[8] = {b0.x, b0.y, b0.z, b0.w, b1.x, b1.y, b1.z, b1.w};
#pragma unroll
            for (int a = 0; a < 2; a++)
#pragma unroll
                for (int i = 0; i < 4; i++)
#pragma unroll
                    for (int b2 = 0; b2 < 2; b2++)
#pragma unroll
                        for (int j = 0; j < 4; j++)
                            acc[a][i][b2][j] = fmaf(ar[a * 4 + i], br[b2 * 4 + j], acc[a][i][b2][j]);
        }
        __syncthreads();
    }

    // epilogue: relu + atomic segment-sum into agg[dst]
#pragma unroll
    for (int a = 0; a < 2; a++)
#pragma unroll
        for (int i = 0; i < 4; i++) {
            int r = a * 64 + ty * 4 + i;
            float* ag = g_agg + (size_t)sDst[r] * HID;
#pragma unroll
            for (int b2 = 0; b2 < 2; b2++)
#pragma unroll
                for (int j = 0; j < 4; j++) {
                    int c = b2 * 64 + tx * 4 + j;
                    float v = acc[a][i][b2][j] + sB[c];
                    if (v > 0.f) atomicAdd(ag + c, v);
                }
        }
}

// ---------------------------------------------------------------- update GEMM
// A[n] = [hn[n] | agg[n]] (K=256) -> hout[n] = relu(A@W + b)
__global__ void __launch_bounds__(256, 2)
upd_gemm(int layer, const float* __restrict__ W, const float* __restrict__ bias)
{
    const float* __restrict__ hn   = layer ? g_hn1 : g_hn0;
    float*       __restrict__ hout = layer ? g_hn0 : g_hn1;
    __shared__ __align__(16) float As[16][132];
    __shared__ __align__(16) float Bs[16][132];
    __shared__ float sB[128];

    const int tid   = threadIdx.x;
    const int nBase = blockIdx.x * 128;
    if (tid < 128) sB[tid] = bias[tid];
    __syncthreads();

    const int arow = tid >> 1;
    const int akl  = (tid & 1) * 8;
    const int tx   = tid & 15, ty = tid >> 4;
    const int nrow = min(nBase + arow, NN - 1);

    float acc[2][4][2][4];
#pragma unroll
    for (int a = 0; a < 2; a++)
#pragma unroll
        for (int i = 0; i < 4; i++)
#pragma unroll
            for (int b2 = 0; b2 < 2; b2++)
#pragma unroll
                for (int j = 0; j < 4; j++) acc[a][i][b2][j] = 0.f;

    float4 apf0, apf1, bpf0, bpf1;
    {
        const float* base = hn + (size_t)nrow * HID;
        apf0 = *(const float4*)(base + akl);
        apf1 = *(const float4*)(base + akl + 4);
        const float4* wb = (const float4*)W;
        bpf0 = wb[tid]; bpf1 = wb[tid + 256];
    }

    for (int t = 0; t < 16; t++) {
        As[akl + 0][arow] = apf0.x; As[akl + 1][arow] = apf0.y;
        As[akl + 2][arow] = apf0.z; As[akl + 3][arow] = apf0.w;
        As[akl + 4][arow] = apf1.x; As[akl + 5][arow] = apf1.y;
        As[akl + 6][arow] = apf1.z; As[akl + 7][arow] = apf1.w;
        {
            int k0 = tid >> 5, c0 = (tid & 31) * 4;
            *(float4*)&Bs[k0][c0]     = bpf0;
            *(float4*)&Bs[k0 + 8][c0] = bpf1;
        }
        __syncthreads();
        if (t < 15) {
            int kb = (t + 1) * 16;
            int seg = kb >> 7, off = kb & 127;
            const float* base = (seg == 0) ? hn + (size_t)nrow * HID + off
                                           : g_agg + (size_t)nrow * HID + off;
            apf0 = *(const float4*)(base + akl);
            apf1 = *(const float4*)(base + akl + 4);
            const float4* wb = (const float4*)(W + (size_t)kb * HID);
            bpf0 = wb[tid]; bpf1 = wb[tid + 256];
        }
#pragma unroll
        for (int k = 0; k < 16; k++) {
            float4 a0 = *(const float4*)&As[k][ty * 4];
            float4 a1 = *(const float4*)&As[k][64 + ty * 4];
            float4 b0 = *(const float4*)&Bs[k][tx * 4];
            float4 b1 = *(const float4*)&Bs[k][64 + tx * 4];
            float ar[8] = {a0.x, a0.y, a0.z, a0.w, a1.x, a1.y, a1.z, a1.w};
            float br[8] = {b0.x, b0.y, b0.z, b0.w, b1.x, b1.y, b1.z, b1.w};
#pragma unroll
            for (int a = 0; a < 2; a++)
#pragma unroll
                for (int i = 0; i < 4; i++)
#pragma unroll
                    for (int b2 = 0; b2 < 2; b2++)
#pragma unroll
                        for (int j = 0; j < 4; j++)
                            acc[a][i][b2][j] = fmaf(ar[a * 4 + i], br[b2 * 4 + j], acc[a][i][b2][j]);
        }
        __syncthreads();
    }

#pragma unroll
    for (int a = 0; a < 2; a++)
#pragma unroll
        for (int i = 0; i < 4; i++) {
            int r = nBase + a * 64 + ty * 4 + i;
            if (r < NN) {
#pragma unroll
                for (int b2 = 0; b2 < 2; b2++)
#pragma unroll
                    for (int j = 0; j < 4; j++) {
                        int c = b2 * 64 + tx * 4 + j;
                        hout[(size_t)r * HID + c] = fmaxf(acc[a][i][b2][j] + sB[c], 0.f);
                    }
            }
        }
}

// --------------------------------------------- fused demand readout (r1+r2+sig)
__global__ void __launch_bounds__(256, 2)
dem_gemm(const int* __restrict__ pairs, const float* __restrict__ dfeat,
         const float* __restrict__ W, const float* __restrict__ bias,
         const float* __restrict__ W2, const float* __restrict__ b2,
         float* __restrict__ out)
{
    const float* __restrict__ hn = g_hn0;
    __shared__ __align__(16) float As[8][132];
    __shared__ __align__(16) float Bs[8][132];
    __shared__ float red[16][132];
    __shared__ int   sS[128], sD[128];
    __shared__ float sB[128], sW2[128];

    const int tid   = threadIdx.x;
    const int dBase = blockIdx.x * 128;
    if (tid < 128) {
        int r = min(dBase + tid, ND - 1);
        sS[tid] = pairs[2 * r]; sD[tid] = pairs[2 * r + 1];
        sB[tid] = bias[tid];    sW2[tid] = W2[tid];
    }
    __syncthreads();

    const int arow = tid >> 1;
    const int akl  = (tid & 1) * 4;
    const int tx   = tid & 15, ty = tid >> 4;
    const int drow = min(dBase + arow, ND - 1);

    float acc[2][4][2][4];
#pragma unroll
    for (int a = 0; a < 2; a++)
#pragma unroll
        for (int i = 0; i < 4; i++)
#pragma unroll
            for (int b2 = 0; b2 < 2; b2++)
#pragma unroll
                for (int j = 0; j < 4; j++) acc[a][i][b2][j] = 0.f;

    float4 apf, bpf;
    {
        apf = *(const float4*)(hn + (size_t)sS[arow] * HID + akl);
        bpf = ((const float4*)W)[tid];
    }

    for (int t = 0; t < 33; t++) {
        As[akl + 0][arow] = apf.x; As[akl + 1][arow] = apf.y;
        As[akl + 2][arow] = apf.z; As[akl + 3][arow] = apf.w;
        {
            int k0 = tid >> 5, c0 = (tid & 31) * 4;
            *(float4*)&Bs[k0][c0] = bpf;
        }
        __syncthreads();
        if (t < 32) {
            int kb = (t + 1) * 8;
            const float* base;
            if      (kb < 128) base = hn + (size_t)sS[arow] * HID + kb;
            else if (kb < 256) base = hn + (size_t)sD[arow] * HID + (kb - 128);
            else               base = dfeat + (size_t)drow * 8;
            apf = *(const float4*)(base + akl);
            bpf = ((const float4*)(W + (size_t)kb * HID))[tid];
        }
#pragma unroll
        for (int k = 0; k < 8; k++) {
            float4 a0 = *(const float4*)&As[k][ty * 4];
            float4 a1 = *(const float4*)&As[k][64 + ty * 4];
            float4 b0 = *(const float4*)&Bs[k][tx * 4];
            float4 b1 = *(const float4*)&Bs[k][64 + tx * 4];
            float ar[8] = {a0.x, a0.y, a0.z, a0.w, a1.x, a1.y, a1.z, a1.w};
            float br[8] = {b0.x, b0.y, b0.z, b0.w, b1.x, b1.y, b1.z, b1.w};
#pragma unroll
            for (int a = 0; a < 2; a++)
#pragma unroll
                for (int i = 0; i < 4; i++)
#pragma unroll
                    for (int b2 = 0; b2 < 2; b2++)
#pragma unroll
                        for (int j = 0; j < 4; j++)
                            acc[a][i][b2][j] = fmaf(ar[a * 4 + i], br[b2 * 4 + j], acc[a][i][b2][j]);
        }
        __syncthreads();
    }

    // relu(hid) dot W_r2, cross-thread reduce, sigmoid
#pragma unroll
    for (int a = 0; a < 2; a++)
#pragma unroll
        for (int i = 0; i < 4; i++) {
            int r = a * 64 + ty * 4 + i;
            float p = 0.f;
#pragma unroll
            for (int b2 = 0; b2 < 2; b2++)
#pragma unroll
                for (int j = 0; j < 4; j++) {
                    int c = b2 * 64 + tx * 4 + j;
                    float h = fmaxf(acc[a][i][b2][j] + sB[c], 0.f);
                    p = fmaf(h, sW2[c], p);
                }
            red[tx][r] = p;
        }
    __syncthreads();
    if (tid < 128) {
        float s = 0.f;
#pragma unroll
        for (int q = 0; q < 16; q++) s += red[q][tid];
        int row = dBase + tid;
        if (row < ND) out[row] = 1.f / (1.f + expf(-(s + b2[0])));
    }
}

// ---------------------------------------------------------------- launch
extern "C" void kernel_launch(void* const* d_in, const int* in_sizes, int n_in,
                              void* d_out, int out_size)
{
    const float* node_feats = (const float*)d_in[0];
    const float* edge_feats = (const float*)d_in[1];
    const float* dem_feats  = (const float*)d_in[2];
    const int*   eidx       = (const int*)d_in[3];
    const int*   pairs      = (const int*)d_in[4];
    const float* W_node = (const float*)d_in[5];
    const float* b_node = (const float*)d_in[6];
    const float* W_edge = (const float*)d_in[7];
    const float* b_edge = (const float*)d_in[8];
    const float* W_msg0 = (const float*)d_in[9];
    const float* b_msg0 = (const float*)d_in[10];
    const float* W_upd0 = (const float*)d_in[11];
    const float* b_upd0 = (const float*)d_in[12];
    const float* W_msg1 = (const float*)d_in[13];
    const float* b_msg1 = (const float*)d_in[14];
    const float* W_upd1 = (const float*)d_in[15];
    const float* b_upd1 = (const float*)d_in[16];
    const float* W_r1   = (const float*)d_in[17];
    const float* b_r1   = (const float*)d_in[18];
    const float* W_r2   = (const float*)d_in[19];
    const float* b_r2   = (const float*)d_in[20];
    float* out = (float*)d_out;

    node_embed<<<NN / 16, 128>>>(node_feats, W_node, b_node);
    edge_embed<<<NE / 64, 128>>>(edge_feats, W_edge, b_edge);

    zero_agg<<<(NN * HID / 4 + 255) / 256, 256>>>();
    msg_gemm<<<NE / 128, 256>>>(0, eidx, W_msg0, b_msg0);
    upd_gemm<<<(NN + 127) / 128, 256>>>(0, W_upd0, b_upd0);

    zero_agg<<<(NN * HID / 4 + 255) / 256, 256>>>();
    msg_gemm<<<NE / 128, 256>>>(1, eidx, W_msg1, b_msg1);
    upd_gemm<<<(NN + 127) / 128, 256>>>(1, W_upd1, b_upd1);

    dem_gemm<<<(ND + 127) / 128, 256>>>(pairs, dem_feats, W_r1, b_r1, W_r2, b_r2, out);
}

// round 2
// speedup vs baseline: 1.9558x; 1.9558x over previous
#include <cuda_runtime.h>
#include <math.h>

#define HID 128
#define NN 20000
#define NE 640000
#define ND 100000

// scratch (device globals: allocation-free contract)
__device__ float g_hn0[(size_t)NN * HID];
__device__ float g_hn1[(size_t)NN * HID];
__device__ float g_agg[(size_t)NN * HID];
__device__ float g_P1 [(size_t)NN * HID];   // also reused as Q1 in readout
__device__ float g_P3 [(size_t)NN * HID];   // also reused as Q2 in readout

// ---------------------------------------------------------------- node embed
__global__ void node_embed(const float* __restrict__ x, const float* __restrict__ W,
                           const float* __restrict__ b)
{
    __shared__ float Ws[32 * HID];
    __shared__ float xs[16][33];
    int tid = threadIdx.x; // 128
    for (int i = tid; i < 32 * HID; i += 128) Ws[i] = W[i];
    int row0 = blockIdx.x * 16;
    for (int i = tid; i < 16 * 32; i += 128) xs[i >> 5][i & 31] = x[(size_t)row0 * 32 + i];
    float bb = b[tid];
    __syncthreads();
#pragma unroll 4
    for (int r = 0; r < 16; r++) {
        float acc = bb;
#pragma unroll
        for (int k = 0; k < 32; k++) acc = fmaf(xs[r][k], Ws[k * HID + tid], acc);
        g_hn0[(size_t)(row0 + r) * HID + tid] = fmaxf(acc, 0.f);
    }
}

// ---------------------------------------------------------------- zero agg
__global__ void zero_agg()
{
    size_t i = (size_t)blockIdx.x * blockDim.x + threadIdx.x;
    if (i < (size_t)NN * HID / 4) ((float4*)g_agg)[i] = make_float4(0.f, 0.f, 0.f, 0.f);
}

// ------------------------------------------------- node-level GEMM (no act)
// out = A @ W,  A: [NN x 128] (selected), W: [128 x 128] row-major
__global__ void __launch_bounds__(256, 2)
gemm128(int asel, int osel, const float* __restrict__ W)
{
    const float* __restrict__ A = asel ? g_hn1 : g_hn0;
    float* __restrict__ out = osel ? g_P3 : g_P1;
    __shared__ __align__(16) float As[16][132];
    __shared__ __align__(16) float Bs[16][132];

    const int tid   = threadIdx.x;
    const int nBase = blockIdx.x * 128;
    const int arow  = tid >> 1;
    const int akl   = (tid & 1) * 8;
    const int tx    = tid & 15, ty = tid >> 4;
    const int nrow  = min(nBase + arow, NN - 1);

    float acc[2][4][2][4];
#pragma unroll
    for (int a = 0; a < 2; a++)
#pragma unroll
        for (int i = 0; i < 4; i++)
#pragma unroll
            for (int b2 = 0; b2 < 2; b2++)
#pragma unroll
                for (int j = 0; j < 4; j++) acc[a][i][b2][j] = 0.f;

    float4 apf0, apf1, bpf0, bpf1;
    {
        const float* base = A + (size_t)nrow * HID;
        apf0 = *(const float4*)(base + akl);
        apf1 = *(const float4*)(base + akl + 4);
        const float4* wb = (const float4*)W;
        bpf0 = wb[tid]; bpf1 = wb[tid + 256];
    }

    for (int t = 0; t < 8; t++) {
        As[akl + 0][arow] = apf0.x; As[akl + 1][arow] = apf0.y;
        As[akl + 2][arow] = apf0.z; As[akl + 3][arow] = apf0.w;
        As[akl + 4][arow] = apf1.x; As[akl + 5][arow] = apf1.y;
        As[akl + 6][arow] = apf1.z; As[akl + 7][arow] = apf1.w;
        {
            int k0 = tid >> 5, c0 = (tid & 31) * 4;
            *(float4*)&Bs[k0][c0]     = bpf0;
            *(float4*)&Bs[k0 + 8][c0] = bpf1;
        }
        __syncthreads();
        if (t < 7) {
            int kb = (t + 1) * 16;
            const float* base = A + (size_t)nrow * HID + kb;
            apf0 = *(const float4*)(base + akl);
            apf1 = *(const float4*)(base + akl + 4);
            const float4* wb = (const float4*)(W + (size_t)kb * HID);
            bpf0 = wb[tid]; bpf1 = wb[tid + 256];
        }
#pragma unroll
        for (int k = 0; k < 16; k++) {
            float4 a0 = *(const float4*)&As[k][ty * 4];
            float4 a1 = *(const float4*)&As[k][64 + ty * 4];
            float4 b0 = *(const float4*)&Bs[k][tx * 4];
            float4 b1 = *(const float4*)&Bs[k][64 + tx * 4];
            float ar[8] = {a0.x, a0.y, a0.z, a0.w, a1.x, a1.y, a1.z, a1.w};
            float br[8] = {b0.x, b0.y, b0.z, b0.w, b1.x, b1.y, b1.z, b1.w};
#pragma unroll
            for (int a = 0; a < 2; a++)
#pragma unroll
                for (int i = 0; i < 4; i++)
#pragma unroll
                    for (int b2 = 0; b2 < 2; b2++)
#pragma unroll
                        for (int j = 0; j < 4; j++)
                            acc[a][i][b2][j] = fmaf(ar[a * 4 + i], br[b2 * 4 + j], acc[a][i][b2][j]);
        }
        __syncthreads();
    }

#pragma unroll
    for (int a = 0; a < 2; a++)
#pragma unroll
        for (int i = 0; i < 4; i++) {
            int r = nBase + a * 64 + ty * 4 + i;
            if (r < NN) {
#pragma unroll
                for (int b2 = 0; b2 < 2; b2++) {
                    int c = b2 * 64 + tx * 4;
                    *(float4*)&out[(size_t)r * HID + c] =
                        make_float4(acc[a][i][b2][0], acc[a][i][b2][1],
                                    acc[a][i][b2][2], acc[a][i][b2][3]);
                }
            }
        }
}

// -------------------------------------- fused edge kernel:
//   he = relu(ef @ We + be)   (recomputed on the fly, per K-chunk)
//   M2 = he @ Wmid            (128x128x128 GEMM per tile)
//   msg = relu(M2 + P1[src] + P3[dst] + bm);  atomicAdd into agg[dst]
__global__ void __launch_bounds__(256, 2)
msg_v2(const int* __restrict__ eidx, const float* __restrict__ ef,
       const float* __restrict__ We, const float* __restrict__ be,
       const float* __restrict__ Wmid, const float* __restrict__ bm)
{
    __shared__ __align__(16) float As[16][132];
    __shared__ __align__(16) float Bs[16][132];
    __shared__ __align__(16) float efs[128][17];
    __shared__ __align__(16) float Wes[16][132];
    __shared__ int   sSrc[128];
    __shared__ int   sDst[128];
    __shared__ float sBm[128];
    __shared__ float beS[128];

    const int tid   = threadIdx.x;
    const int eBase = blockIdx.x * 128;

    if (tid < 128) { sSrc[tid] = eidx[eBase + tid]; sBm[tid] = bm[tid]; }
    else           { sDst[tid - 128] = eidx[NE + eBase + tid - 128]; beS[tid - 128] = be[tid - 128]; }
    // stage ef tile [128 x 16]
    {
        const float4* eg = (const float4*)(ef + (size_t)eBase * 16);
#pragma unroll
        for (int u = 0; u < 2; u++) {
            int g = tid * 2 + u;                 // 0..511
            float4 v = eg[g];
            int row = g >> 2, c = (g & 3) * 4;
            efs[row][c + 0] = v.x; efs[row][c + 1] = v.y;
            efs[row][c + 2] = v.z; efs[row][c + 3] = v.w;
        }
    }
    // stage We [16 x 128]
    {
        const float4* wg = (const float4*)We;
#pragma unroll
        for (int u = 0; u < 2; u++) {
            int g = tid * 2 + u;                 // 0..511
            int row = g >> 5, c = (g & 31) * 4;
            *(float4*)&Wes[row][c] = wg[g];
        }
    }
    __syncthreads();

    const int arow = tid >> 1;
    const int akl  = (tid & 1) * 8;
    const int tx   = tid & 15, ty = tid >> 4;

    float acc[2][4][2][4];
#pragma unroll
    for (int a = 0; a < 2; a++)
#pragma unroll
        for (int i = 0; i < 4; i++)
#pragma unroll
            for (int b2 = 0; b2 < 2; b2++)
#pragma unroll
                for (int j = 0; j < 4; j++) acc[a][i][b2][j] = 0.f;

    float an[8];
    float4 bpf0, bpf1;
    // compute A-chunk 0 (he columns akl..akl+7) + prefetch B-chunk 0
    {
        int kg = akl;
#pragma unroll
        for (int i = 0; i < 8; i++) an[i] = beS[kg + i];
#pragma unroll
        for (int q = 0; q < 16; q++) {
            float e = efs[arow][q];
            float4 w0 = *(const float4*)&Wes[q][kg];
            float4 w1 = *(const float4*)&Wes[q][kg + 4];
            an[0] = fmaf(e, w0.x, an[0]); an[1] = fmaf(e, w0.y, an[1]);
            an[2] = fmaf(e, w0.z, an[2]); an[3] = fmaf(e, w0.w, an[3]);
            an[4] = fmaf(e, w1.x, an[4]); an[5] = fmaf(e, w1.y, an[5]);
            an[6] = fmaf(e, w1.z, an[6]); an[7] = fmaf(e, w1.w, an[7]);
        }
#pragma unroll
        for (int i = 0; i < 8; i++) an[i] = fmaxf(an[i], 0.f);
        const float4* wb = (const float4*)Wmid;
        bpf0 = wb[tid]; bpf1 = wb[tid + 256];
    }

    for (int t = 0; t < 8; t++) {
#pragma unroll
        for (int i = 0; i < 8; i++) As[akl + i][arow] = an[i];
        {
            int k0 = tid >> 5, c0 = (tid & 31) * 4;
            *(float4*)&Bs[k0][c0]     = bpf0;
            *(float4*)&Bs[k0 + 8][c0] = bpf1;
        }
        __syncthreads();
        if (t < 7) {
            int kb = (t + 1) * 16;
            const float4* wb = (const float4*)(Wmid + (size_t)kb * HID);
            bpf0 = wb[tid]; bpf1 = wb[tid + 256];
            int kg = kb + akl;
#pragma unroll
            for (int i = 0; i < 8; i++) an[i] = beS[kg + i];
#pragma unroll
            for (int q = 0; q < 16; q++) {
                float e = efs[arow][q];
                float4 w0 = *(const float4*)&Wes[q][kg];
                float4 w1 = *(const float4*)&Wes[q][kg + 4];
                an[0] = fmaf(e, w0.x, an[0]); an[1] = fmaf(e, w0.y, an[1]);
                an[2] = fmaf(e, w0.z, an[2]); an[3] = fmaf(e, w0.w, an[3]);
                an[4] = fmaf(e, w1.x, an[4]); an[5] = fmaf(e, w1.y, an[5]);
                an[6] = fmaf(e, w1.z, an[6]); an[7] = fmaf(e, w1.w, an[7]);
            }
#pragma unroll
            for (int i = 0; i < 8; i++) an[i] = fmaxf(an[i], 0.f);
        }
#pragma unroll
        for (int k = 0; k < 16; k++) {
            float4 a0 = *(const float4*)&As[k][ty * 4];
            float4 a1 = *(const float4*)&As[k][64 + ty * 4];
            float4 b0 = *(const float4*)&Bs[k][tx * 4];
            float4 b1 = *(const float4*)&Bs[k][64 + tx * 4];
            float ar[8] = {a0.x, a0.y, a0.z, a0.w, a1.x, a1.y, a1.z, a1.w};
            float br[8] = {b0.x, b0.y, b0.z, b0.w, b1.x, b1.y, b1.z, b1.w};
#pragma unroll
            for (int a = 0; a < 2; a++)
#pragma unroll
                for (int i = 0; i < 4; i++)
#pragma unroll
                    for (int b2 = 0; b2 < 2; b2++)
#pragma unroll
                        for (int j = 0; j < 4; j++)
                            acc[a][i][b2][j] = fmaf(ar[a * 4 + i], br[b2 * 4 + j], acc[a][i][b2][j]);
        }
        __syncthreads();
    }

    // epilogue: + P1[src] + P3[dst] + bias, relu, atomic segment-sum into agg[dst]
#pragma unroll
    for (int a = 0; a < 2; a++)
#pragma unroll
        for (int i = 0; i < 4; i++) {
            int r = a * 64 + ty * 4 + i;
            const float* p1 = g_P1 + (size_t)sSrc[r] * HID;
            const float* p3 = g_P3 + (size_t)sDst[r] * HID;
            float* ag = g_agg + (size_t)sDst[r] * HID;
#pragma unroll
            for (int b2 = 0; b2 < 2; b2++) {
                int c = b2 * 64 + tx * 4;
                float4 v1 = *(const float4*)(p1 + c);
                float4 v3 = *(const float4*)(p3 + c);
                float v[4];
                v[0] = acc[a][i][b2][0] + sBm[c + 0] + v1.x + v3.x;
                v[1] = acc[a][i][b2][1] + sBm[c + 1] + v1.y + v3.y;
                v[2] = acc[a][i][b2][2] + sBm[c + 2] + v1.z + v3.z;
                v[3] = acc[a][i][b2][3] + sBm[c + 3] + v1.w + v3.w;
#pragma unroll
                for (int j = 0; j < 4; j++)
                    if (v[j] > 0.f) atomicAdd(ag + c + j, v[j]);
            }
        }
}

// ---------------------------------------------------------------- update GEMM
// A[n] = [hn[n] | agg[n]] (K=256) -> hout[n] = relu(A@W + b)
__global__ void __launch_bounds__(256, 2)
upd_gemm(int layer, const float* __restrict__ W, const float* __restrict__ bias)
{
    const float* __restrict__ hn   = layer ? g_hn1 : g_hn0;
    float*       __restrict__ hout = layer ? g_hn0 : g_hn1;
    __shared__ __align__(16) float As[16][132];
    __shared__ __align__(16) float Bs[16][132];
    __shared__ float sB[128];

    const int tid   = threadIdx.x;
    const int nBase = blockIdx.x * 128;
    if (tid < 128) sB[tid] = bias[tid];
    __syncthreads();

    const int arow = tid >> 1;
    const int akl  = (tid & 1) * 8;
    const int tx   = tid & 15, ty = tid >> 4;
    const int nrow = min(nBase + arow, NN - 1);

    float acc[2][4][2][4];
#pragma unroll
    for (int a = 0; a < 2; a++)
#pragma unroll
        for (int i = 0; i < 4; i++)
#pragma unroll
            for (int b2 = 0; b2 < 2; b2++)
#pragma unroll
                for (int j = 0; j < 4; j++) acc[a][i][b2][j] = 0.f;

    float4 apf0, apf1, bpf0, bpf1;
    {
        const float* base = hn + (size_t)nrow * HID;
        apf0 = *(const float4*)(base + akl);
        apf1 = *(const float4*)(base + akl + 4);
        const float4* wb = (const float4*)W;
        bpf0 = wb[tid]; bpf1 = wb[tid + 256];
    }

    for (int t = 0; t < 16; t++) {
        As[akl + 0][arow] = apf0.x; As[akl + 1][arow] = apf0.y;
        As[akl + 2][arow] = apf0.z; As[akl + 3][arow] = apf0.w;
        As[akl + 4][arow] = apf1.x; As[akl + 5][arow] = apf1.y;
        As[akl + 6][arow] = apf1.z; As[akl + 7][arow] = apf1.w;
        {
            int k0 = tid >> 5, c0 = (tid & 31) * 4;
            *(float4*)&Bs[k0][c0]     = bpf0;
            *(float4*)&Bs[k0 + 8][c0] = bpf1;
        }
        __syncthreads();
        if (t < 15) {
            int kb = (t + 1) * 16;
            int seg = kb >> 7, off = kb & 127;
            const float* base = (seg == 0) ? hn + (size_t)nrow * HID + off
                                           : g_agg + (size_t)nrow * HID + off;
            apf0 = *(const float4*)(base + akl);
            apf1 = *(const float4*)(base + akl + 4);
            const float4* wb = (const float4*)(W + (size_t)kb * HID);
            bpf0 = wb[tid]; bpf1 = wb[tid + 256];
        }
#pragma unroll
        for (int k = 0; k < 16; k++) {
            float4 a0 = *(const float4*)&As[k][ty * 4];
            float4 a1 = *(const float4*)&As[k][64 + ty * 4];
            float4 b0 = *(const float4*)&Bs[k][tx * 4];
            float4 b1 = *(const float4*)&Bs[k][64 + tx * 4];
            float ar[8] = {a0.x, a0.y, a0.z, a0.w, a1.x, a1.y, a1.z, a1.w};
            float br[8] = {b0.x, b0.y, b0.z, b0.w, b1.x, b1.y, b1.z, b1.w};
#pragma unroll
            for (int a = 0; a < 2; a++)
#pragma unroll
                for (int i = 0; i < 4; i++)
#pragma unroll
                    for (int b2 = 0; b2 < 2; b2++)
#pragma unroll
                        for (int j = 0; j < 4; j++)
                            acc[a][i][b2][j] = fmaf(ar[a * 4 + i], br[b2 * 4 + j], acc[a][i][b2][j]);
        }
        __syncthreads();
    }

#pragma unroll
    for (int a = 0; a < 2; a++)
#pragma unroll
        for (int i = 0; i < 4; i++) {
            int r = nBase + a * 64 + ty * 4 + i;
            if (r < NN) {
#pragma unroll
                for (int b2 = 0; b2 < 2; b2++)
#pragma unroll
                    for (int j = 0; j < 4; j++) {
                        int c = b2 * 64 + tx * 4 + j;
                        hout[(size_t)r * HID + c] = fmaxf(acc[a][i][b2][j] + sB[c], 0.f);
                    }
            }
        }
}

// --------------------------------------------- fused demand readout
// hid = relu(Q1[ds] + Q2[dd] + dfeat@Wd + b); out = sigmoid(hid . w2 + b2)
__global__ void __launch_bounds__(256)
dem_v2(const int* __restrict__ pairs, const float* __restrict__ dfeat,
       const float* __restrict__ Wd, const float* __restrict__ br1,
       const float* __restrict__ w2, const float* __restrict__ b2,
       float* __restrict__ out)
{
    __shared__ __align__(16) float Wds[8][132];
    __shared__ float w2s[128], bs[128];
    int tid = threadIdx.x;
    if (tid < 128) { w2s[tid] = w2[tid]; bs[tid] = br1[tid]; }
    {
        int row = tid >> 5, c = (tid & 31) * 4;
        *(float4*)&Wds[row][c] = ((const float4*)Wd)[tid];
    }
    __syncthreads();

    int w = tid >> 5, lane = tid & 31;
    int d = blockIdx.x * 8 + w;
    int ds = pairs[2 * d], dd = pairs[2 * d + 1];
    int c0 = lane * 4;

    float4 q1 = *(const float4*)(g_P1 + (size_t)ds * HID + c0);
    float4 q2 = *(const float4*)(g_P3 + (size_t)dd * HID + c0);
    float s0 = bs[c0 + 0] + q1.x + q2.x;
    float s1 = bs[c0 + 1] + q1.y + q2.y;
    float s2 = bs[c0 + 2] + q1.z + q2.z;
    float s3 = bs[c0 + 3] + q1.w + q2.w;
#pragma unroll
    for (int q = 0; q < 8; q++) {
        float e = dfeat[(size_t)d * 8 + q];
        float4 wv = *(const float4*)&Wds[q][c0];
        s0 = fmaf(e, wv.x, s0); s1 = fmaf(e, wv.y, s1);
        s2 = fmaf(e, wv.z, s2); s3 = fmaf(e, wv.w, s3);
    }
    float p = fmaxf(s0, 0.f) * w2s[c0 + 0] + fmaxf(s1, 0.f) * w2s[c0 + 1]
            + fmaxf(s2, 0.f) * w2s[c0 + 2] + fmaxf(s3, 0.f) * w2s[c0 + 3];
#pragma unroll
    for (int o = 16; o > 0; o >>= 1) p += __shfl_xor_sync(0xffffffffu, p, o);
    if (lane == 0) out[d] = 1.f / (1.f + expf(-(p + b2[0])));
}

// ---------------------------------------------------------------- launch
extern "C" void kernel_launch(void* const* d_in, const int* in_sizes, int n_in,
                              void* d_out, int out_size)
{
    const float* node_feats = (const float*)d_in[0];
    const float* edge_feats = (const float*)d_in[1];
    const float* dem_feats  = (const float*)d_in[2];
    const int*   eidx       = (const int*)d_in[3];
    const int*   pairs      = (const int*)d_in[4];
    const float* W_node = (const float*)d_in[5];
    const float* b_node = (const float*)d_in[6];
    const float* W_edge = (const float*)d_in[7];
    const float* b_edge = (const float*)d_in[8];
    const float* W_msg0 = (const float*)d_in[9];
    const float* b_msg0 = (const float*)d_in[10];
    const float* W_upd0 = (const float*)d_in[11];
    const float* b_upd0 = (const float*)d_in[12];
    const float* W_msg1 = (const float*)d_in[13];
    const float* b_msg1 = (const float*)d_in[14];
    const float* W_upd1 = (const float*)d_in[15];
    const float* b_upd1 = (const float*)d_in[16];
    const float* W_r1   = (const float*)d_in[17];
    const float* b_r1   = (const float*)d_in[18];
    const float* W_r2   = (const float*)d_in[19];
    const float* b_r2   = (const float*)d_in[20];
    float* out = (float*)d_out;

    const int nTiles = (NN + 127) / 128;

    node_embed<<<NN / 16, 128>>>(node_feats, W_node, b_node);

    // ---- layer 0
    gemm128<<<nTiles, 256>>>(0, 0, W_msg0);                 // P1 = hn0 @ Wm0[0:128]
    gemm128<<<nTiles, 256>>>(0, 1, W_msg0 + 256 * HID);     // P3 = hn0 @ Wm0[256:384]
    zero_agg<<<(NN * HID / 4 + 255) / 256, 256>>>();
    msg_v2<<<NE / 128, 256>>>(eidx, edge_feats, W_edge, b_edge,
                              W_msg0 + 128 * HID, b_msg0);
    upd_gemm<<<nTiles, 256>>>(0, W_upd0, b_upd0);

    // ---- layer 1
    gemm128<<<nTiles, 256>>>(1, 0, W_msg1);                 // P1 = hn1 @ Wm1[0:128]
    gemm128<<<nTiles, 256>>>(1, 1, W_msg1 + 256 * HID);     // P3 = hn1 @ Wm1[256:384]
    zero_agg<<<(NN * HID / 4 + 255) / 256, 256>>>();
    msg_v2<<<NE / 128, 256>>>(eidx, edge_feats, W_edge, b_edge,
                              W_msg1 + 128 * HID, b_msg1);
    upd_gemm<<<nTiles, 256>>>(1, W_upd1, b_upd1);

    // ---- readout
    gemm128<<<nTiles, 256>>>(0, 0, W_r1);                   // Q1 = hn @ Wr1[0:128]
    gemm128<<<nTiles, 256>>>(0, 1, W_r1 + 128 * HID);       // Q2 = hn @ Wr1[128:256]
    dem_v2<<<ND / 8, 256>>>(pairs, dem_feats, W_r1 + 256 * HID, b_r1, W_r2, b_r2, out);
}